// round 13
// baseline (speedup 1.0000x reference)
#include <cuda_runtime.h>
#include <math.h>

#define N0 2048
#define N1 1024
#define K0 16               // 9 (A) + 3 (G diag) + 3 (2*G upper) + 1 pad
#define K1 40               // 25 (A) + 5 (G diag) + 10 (2*G upper)
// All tiles 64x64, 128-thread blocks, micro-tile 4x8 (16x8 thread grid)
#define NBT0 (N0 / 64)      // 32
#define NBT1 (N1 / 64)      // 16
#define NTILE0 (NBT0 * (NBT0 + 1) / 2)   // 528
#define NTILE1 (NBT1 * (NBT1 + 1) / 2)   // 136
#define GRID_ALL (NTILE0 + NTILE1)       // 664

// Only cross-block state: accumulators + completion counter (self-cleaned)
__device__ double   g_acc0 = 0.0;
__device__ double   g_acc1 = 0.0;
__device__ unsigned g_count = 0u;

// relu(1 - sqrt(d2)) via rsqrt (only called on the rare d2 < 1 path)
__device__ __forceinline__ float loss_term(float d2) {
    float s = fmaxf(d2, 1e-20f);
    return fmaxf(1.0f - s * __frsqrt_rn(s), 0.0f);
}

// Swizzled K-major store: dst[k][col] at k*64 + ((col>>2 ^ k>>2)<<2) + (col&3)
__device__ __forceinline__ void sts_sw(float* dst, int col, int k, float v) {
    dst[k * 64 + ((((col >> 2) ^ (k >> 2)) << 2) + (col & 3))] = v;
}

// ---------------------------------------------------------------------------
// layer-0 prep (3x3).  U row: [A(9), G_diag(3), 2*G_upper(3), pad]
//                      V row: [-2*B^T(9), H_diag(3), H_upper(3), pad]
// dot(U,V) = -2 tr(AB) + tr(G H);  diff^2 = 3 + dot
// ---------------------------------------------------------------------------
__device__ __forceinline__ void prep3_U(const float* __restrict__ in0, int i,
                                        float* dst, int col) {
    float a[9];
    float ss = 0.f;
#pragma unroll
    for (int k = 0; k < 9; k++) { a[k] = in0[i * 9 + k]; ss += a[k] * a[k]; }
    float inv_n = 1.0f / (sqrtf(ss) + 1e-8f);
#pragma unroll
    for (int k = 0; k < 9; k++) a[k] *= inv_n;

    float c00 = a[4] * a[8] - a[5] * a[7];
    float c01 = a[5] * a[6] - a[3] * a[8];
    float c02 = a[3] * a[7] - a[4] * a[6];
    float det = a[0] * c00 + a[1] * c01 + a[2] * c02;
    float id  = 1.0f / det;

    float v[9];
    v[0] = c00 * id;
    v[1] = (a[2] * a[7] - a[1] * a[8]) * id;
    v[2] = (a[1] * a[5] - a[2] * a[4]) * id;
    v[3] = c01 * id;
    v[4] = (a[0] * a[8] - a[2] * a[6]) * id;
    v[5] = (a[2] * a[3] - a[0] * a[5]) * id;
    v[6] = c02 * id;
    v[7] = (a[1] * a[6] - a[0] * a[7]) * id;
    v[8] = (a[0] * a[4] - a[1] * a[3]) * id;

#pragma unroll
    for (int k = 0; k < 9; k++) sts_sw(dst, col, k, v[k]);
#pragma unroll
    for (int d = 0; d < 3; d++) {
        float s = 0.f;
#pragma unroll
        for (int k = 0; k < 3; k++) s += v[k * 3 + d] * v[k * 3 + d];
        sts_sw(dst, col, 9 + d, s);
    }
    {
        int idx = 0;
#pragma unroll
        for (int r = 0; r < 3; r++)
#pragma unroll
            for (int c = r + 1; c < 3; c++) {
                float s = 0.f;
#pragma unroll
                for (int k = 0; k < 3; k++) s += v[k * 3 + r] * v[k * 3 + c];
                sts_sw(dst, col, 12 + idx, 2.0f * s);
                idx++;
            }
    }
    sts_sw(dst, col, 15, 0.f);
}

__device__ __forceinline__ void prep3_V(const float* __restrict__ in0, int j,
                                        float* dst, int col) {
    float a[9];
    float ss = 0.f;
#pragma unroll
    for (int k = 0; k < 9; k++) { a[k] = in0[j * 9 + k]; ss += a[k] * a[k]; }
    float inv_n = 1.0f / (sqrtf(ss) + 1e-8f);
#pragma unroll
    for (int k = 0; k < 9; k++) a[k] *= inv_n;

#pragma unroll
    for (int r = 0; r < 3; r++)
#pragma unroll
        for (int k = 0; k < 3; k++)
            sts_sw(dst, col, r * 3 + k, -2.0f * a[k * 3 + r]);
#pragma unroll
    for (int d = 0; d < 3; d++) {
        float s = 0.f;
#pragma unroll
        for (int k = 0; k < 3; k++) s += a[d * 3 + k] * a[d * 3 + k];
        sts_sw(dst, col, 9 + d, s);
    }
    {
        int idx = 0;
#pragma unroll
        for (int r = 0; r < 3; r++)
#pragma unroll
            for (int c = r + 1; c < 3; c++) {
                float s = 0.f;
#pragma unroll
                for (int k = 0; k < 3; k++) s += a[r * 3 + k] * a[c * 3 + k];
                sts_sw(dst, col, 12 + idx, s);
                idx++;
            }
    }
    sts_sw(dst, col, 15, 0.f);
}

// ---------------------------------------------------------------------------
// layer-1 prep (5x5).  U row: [A(25), G_diag(5), 2*G_upper(10)]  (K1 = 40)
//                      V row: [-2*B^T(25), H_diag(5), H_upper(10)]
// ---------------------------------------------------------------------------
__device__ __forceinline__ void prep5_U(const float* __restrict__ in1, int i,
                                        float* dst, int col) {
    float m[5][10];
    float ss = 0.f;
#pragma unroll
    for (int r = 0; r < 5; r++)
#pragma unroll
        for (int c = 0; c < 5; c++) {
            float x = in1[i * 25 + r * 5 + c];
            m[r][c] = x; ss += x * x;
            m[r][c + 5] = (r == c) ? 1.0f : 0.0f;
        }
    float inv_n = 1.0f / (sqrtf(ss) + 1e-8f);
#pragma unroll
    for (int r = 0; r < 5; r++)
#pragma unroll
        for (int c = 0; c < 5; c++) m[r][c] *= inv_n;

#pragma unroll
    for (int col_ = 0; col_ < 5; col_++) {
#pragma unroll
        for (int r2 = 0; r2 < 5; r2++) {
            if (r2 > col_) {
                bool sw = fabsf(m[r2][col_]) > fabsf(m[col_][col_]);
#pragma unroll
                for (int c = 0; c < 10; c++) {
                    float x = m[col_][c], y = m[r2][c];
                    m[col_][c] = sw ? y : x;
                    m[r2][c]   = sw ? x : y;
                }
            }
        }
        float piv = 1.0f / m[col_][col_];
#pragma unroll
        for (int c = 0; c < 10; c++) m[col_][c] *= piv;
#pragma unroll
        for (int r = 0; r < 5; r++) {
            if (r == col_) continue;
            float f = m[r][col_];
#pragma unroll
            for (int c = 0; c < 10; c++) m[r][c] = fmaf(-f, m[col_][c], m[r][c]);
        }
    }

#pragma unroll
    for (int r = 0; r < 5; r++)
#pragma unroll
        for (int c = 0; c < 5; c++)
            sts_sw(dst, col, r * 5 + c, m[r][c + 5]);
#pragma unroll
    for (int d = 0; d < 5; d++) {
        float s = 0.f;
#pragma unroll
        for (int k = 0; k < 5; k++) s += m[k][d + 5] * m[k][d + 5];
        sts_sw(dst, col, 25 + d, s);
    }
    {
        int idx = 0;
#pragma unroll
        for (int r = 0; r < 5; r++)
#pragma unroll
            for (int c = r + 1; c < 5; c++) {
                float s = 0.f;
#pragma unroll
                for (int k = 0; k < 5; k++) s += m[k][r + 5] * m[k][c + 5];
                sts_sw(dst, col, 30 + idx, 2.0f * s);
                idx++;
            }
    }
}

__device__ __forceinline__ void prep5_V(const float* __restrict__ in1, int j,
                                        float* dst, int col) {
    float b[25];
    float ss = 0.f;
#pragma unroll
    for (int k = 0; k < 25; k++) { b[k] = in1[j * 25 + k]; ss += b[k] * b[k]; }
    float inv_n = 1.0f / (sqrtf(ss) + 1e-8f);
#pragma unroll
    for (int k = 0; k < 25; k++) b[k] *= inv_n;

#pragma unroll
    for (int r = 0; r < 5; r++)
#pragma unroll
        for (int k = 0; k < 5; k++)
            sts_sw(dst, col, r * 5 + k, -2.0f * b[k * 5 + r]);
#pragma unroll
    for (int d = 0; d < 5; d++) {
        float s = 0.f;
#pragma unroll
        for (int k = 0; k < 5; k++) s += b[d * 5 + k] * b[d * 5 + k];
        sts_sw(dst, col, 25 + d, s);
    }
    {
        int idx = 0;
#pragma unroll
        for (int r = 0; r < 5; r++)
#pragma unroll
            for (int c = r + 1; c < 5; c++) {
                float s = 0.f;
#pragma unroll
                for (int k = 0; k < 5; k++) s += b[r * 5 + k] * b[c * 5 + k];
                sts_sw(dst, col, 30 + idx, s);
                idx++;
            }
    }
}

// ---------------------------------------------------------------------------
// Shared mainloop + epilogue for a 64x64 tile, micro 4x8 (128 threads).
// LAYER: 0 -> K=16, D=3 ; 1 -> K=40, D=5
// ---------------------------------------------------------------------------
template <int LAYER>
__device__ __forceinline__ float tile_mainloop(const float* Us, const float* Vs,
                                               int i0, int j0, bool diag, int tid) {
    constexpr int K = LAYER ? K1 : K0;
    constexpr float D = LAYER ? 5.0f : 3.0f;

    int tx = tid & 7, ty = tid >> 3;   // 8 cols-groups x 16 row-groups
    float acc[32];
#pragma unroll
    for (int q = 0; q < 32; q++) acc[q] = 0.f;

#pragma unroll 4
    for (int k = 0; k < K; k++) {
        int kc = k >> 2;
        float4 a  = *(const float4*)&Us[k * 64 + ((ty ^ kc) << 2)];
        float4 bA = *(const float4*)&Vs[k * 64 + ((((2 * tx) ^ kc)) << 2)];
        float4 bB = *(const float4*)&Vs[k * 64 + ((((2 * tx + 1) ^ kc)) << 2)];
#pragma unroll
        for (int r = 0; r < 4; r++) {
            float av = (r == 0) ? a.x : (r == 1) ? a.y : (r == 2) ? a.z : a.w;
            acc[r * 8 + 0] = fmaf(av, bA.x, acc[r * 8 + 0]);
            acc[r * 8 + 1] = fmaf(av, bA.y, acc[r * 8 + 1]);
            acc[r * 8 + 2] = fmaf(av, bA.z, acc[r * 8 + 2]);
            acc[r * 8 + 3] = fmaf(av, bA.w, acc[r * 8 + 3]);
            acc[r * 8 + 4] = fmaf(av, bB.x, acc[r * 8 + 4]);
            acc[r * 8 + 5] = fmaf(av, bB.y, acc[r * 8 + 5]);
            acc[r * 8 + 6] = fmaf(av, bB.z, acc[r * 8 + 6]);
            acc[r * 8 + 7] = fmaf(av, bB.w, acc[r * 8 + 7]);
        }
    }

    // min-scan early-out: any d2 = D + acc < 1  <=>  min(acc) < 1 - D
    float mn = acc[0];
#pragma unroll
    for (int q = 1; q < 32; q++) mn = fminf(mn, acc[q]);

    float val = 0.f;
    if (mn < 1.0f - D) {
        if (!diag) {
#pragma unroll
            for (int q = 0; q < 32; q++) val += loss_term(D + acc[q]);
        } else {
            int ib = i0 + ty * 4;
            // logical columns of acc[r*8+c]: c<4 -> j0+8*tx+c ; c>=4 -> j0+8*tx+4+(c-4)
#pragma unroll
            for (int r = 0; r < 4; r++)
#pragma unroll
                for (int c = 0; c < 8; c++) {
                    int j = j0 + 8 * tx + c;
                    if (ib + r > j) val += loss_term(D + acc[r * 8 + c]);
                }
        }
    }
    return val;
}

// triangle decode (incl diagonal): t -> (by, bx), by >= bx
__device__ __forceinline__ void tri_decode(int t, int& by, int& bx) {
    int r = 0;
    while ((r + 1) * (r + 2) / 2 <= t) r++;
    by = r;
    bx = t - r * (r + 1) / 2;
}

// ---------------------------------------------------------------------------
// Fully self-contained blocks: redundant prep -> GEMM -> reduce -> finalize
// ---------------------------------------------------------------------------
__global__ __launch_bounds__(128, 8) void fused_kernel(const float* __restrict__ in0,
                                                       const float* __restrict__ in1,
                                                       float* __restrict__ out) {
    __shared__ float smem[2 * K1 * 64];   // 20 KB (layer1 worst case)
    int tid = threadIdx.x;
    int b = blockIdx.x;

    float* Us = smem;
    float* Vs = smem + (b < NTILE1 ? K1 : K0) * 64;

    float val;
    bool layer1 = (b < NTILE1);           // heavier tiles on low block ids
    if (layer1) {
        int by, bx; tri_decode(b, by, bx);
        int i0 = by * 64, j0 = bx * 64;
        if (tid < 64) prep5_U(in1, i0 + tid, Us, tid);
        else          prep5_V(in1, j0 + tid - 64, Vs, tid - 64);
        __syncthreads();
        val = tile_mainloop<1>(Us, Vs, i0, j0, by == bx, tid);
    } else {
        int by, bx; tri_decode(b - NTILE1, by, bx);
        int i0 = by * 64, j0 = bx * 64;
        if (tid < 64) prep3_U(in0, i0 + tid, Us, tid);
        else          prep3_V(in0, j0 + tid - 64, Vs, tid - 64);
        __syncthreads();
        val = tile_mainloop<0>(Us, Vs, i0, j0, by == bx, tid);
    }

#pragma unroll
    for (int o = 16; o > 0; o >>= 1)
        val += __shfl_down_sync(0xffffffffu, val, o);

    __syncthreads();   // smem main-loop reads done before reuse
    if ((tid & 31) == 0) smem[tid >> 5] = val;
    __syncthreads();

    if (tid == 0) {
        float s = smem[0] + smem[1] + smem[2] + smem[3];
        if (s != 0.0f)
            atomicAdd(layer1 ? &g_acc1 : &g_acc0, (double)s);
        __threadfence();
        unsigned done = atomicAdd(&g_count, 1u) + 1u;
        if (done == (unsigned)GRID_ALL) {
            double a0 = atomicAdd(&g_acc0, 0.0);
            double a1 = atomicAdd(&g_acc1, 0.0);
            double l0 = 2.0 * a0 / ((double)N0 * (double)(N0 - 1));
            double l1 = 2.0 * a1 / ((double)N1 * (double)(N1 - 1));
            out[0] = (float)(0.5 * (l0 + l1));
            // self-clean for the next graph replay (zero-invariant at entry)
            g_acc0 = 0.0; g_acc1 = 0.0;
            __threadfence();
            g_count = 0u;
        }
    }
}

extern "C" void kernel_launch(void* const* d_in, const int* in_sizes, int n_in,
                              void* d_out, int out_size) {
    const float* k0 = (const float*)d_in[0];
    const float* k1 = (const float*)d_in[1];
    float* out = (float*)d_out;
    fused_kernel<<<GRID_ALL, 128>>>(k0, k1, out);
}

// round 16
// speedup vs baseline: 1.3383x; 1.3383x over previous
#include <cuda_runtime.h>
#include <math.h>

#define N0 2048
#define N1 1024
#define K0 16               // 9 (A) + 3 (G diag) + 3 (2*G upper) + 1 pad
#define K1 40               // 25 (A) + 5 (G diag) + 10 (2*G upper)
// All tiles 32 rows x 64 cols, 128-thread blocks, micro-tile 4x4 (8x16 grid)
// layer0: by 0..63 (32-row), bx 0..31 (64-col), by >= 2*bx : 1056 tiles
// layer1: by 0..31, bx 0..15, by >= 2*bx : 272 tiles
#define NBY0 (N0 / 32)      // 64
#define NBX0 (N0 / 64)      // 32
#define NBY1 (N1 / 32)      // 32
#define NBX1 (N1 / 64)      // 16
#define NTILE0 1056
#define NTILE1 272
#define GRID_ALL (NTILE0 + NTILE1)   // 1328

// Only cross-block state: accumulators + completion counter (self-cleaned)
__device__ double   g_acc0 = 0.0;
__device__ double   g_acc1 = 0.0;
__device__ unsigned g_count = 0u;

// relu(1 - sqrt(d2)) via rsqrt (only called on the rare d2 < 1 path)
__device__ __forceinline__ float loss_term(float d2) {
    float s = fmaxf(d2, 1e-20f);
    return fmaxf(1.0f - s * __frsqrt_rn(s), 0.0f);
}

// Swizzled K-major stores.  U tile width 32 (8 chunks), V tile width 64 (16).
__device__ __forceinline__ void sts_swU(float* dst, int col, int k, float v) {
    dst[k * 32 + ((((col >> 2) ^ (k >> 2)) & 7) << 2) + (col & 3)] = v;
}
__device__ __forceinline__ void sts_swV(float* dst, int col, int k, float v) {
    dst[k * 64 + ((((col >> 2) ^ (k >> 2)) & 15) << 2) + (col & 3)] = v;
}

// ---------------------------------------------------------------------------
// layer-0 prep (3x3).  U row: [A(9), G_diag(3), 2*G_upper(3), pad]
//                      V row: [-2*B^T(9), H_diag(3), H_upper(3), pad]
// dot(U,V) = -2 tr(AB) + tr(G H);  diff^2 = 3 + dot
// ---------------------------------------------------------------------------
__device__ __forceinline__ void prep3_U(const float* __restrict__ in0, int i,
                                        float* dst, int col) {
    float a[9];
    float ss = 0.f;
#pragma unroll
    for (int k = 0; k < 9; k++) { a[k] = in0[i * 9 + k]; ss += a[k] * a[k]; }
    float inv_n = 1.0f / (sqrtf(ss) + 1e-8f);
#pragma unroll
    for (int k = 0; k < 9; k++) a[k] *= inv_n;

    float c00 = a[4] * a[8] - a[5] * a[7];
    float c01 = a[5] * a[6] - a[3] * a[8];
    float c02 = a[3] * a[7] - a[4] * a[6];
    float det = a[0] * c00 + a[1] * c01 + a[2] * c02;
    float id  = 1.0f / det;

    float v[9];
    v[0] = c00 * id;
    v[1] = (a[2] * a[7] - a[1] * a[8]) * id;
    v[2] = (a[1] * a[5] - a[2] * a[4]) * id;
    v[3] = c01 * id;
    v[4] = (a[0] * a[8] - a[2] * a[6]) * id;
    v[5] = (a[2] * a[3] - a[0] * a[5]) * id;
    v[6] = c02 * id;
    v[7] = (a[1] * a[6] - a[0] * a[7]) * id;
    v[8] = (a[0] * a[4] - a[1] * a[3]) * id;

#pragma unroll
    for (int k = 0; k < 9; k++) sts_swU(dst, col, k, v[k]);
#pragma unroll
    for (int d = 0; d < 3; d++) {
        float s = 0.f;
#pragma unroll
        for (int k = 0; k < 3; k++) s += v[k * 3 + d] * v[k * 3 + d];
        sts_swU(dst, col, 9 + d, s);
    }
    {
        int idx = 0;
#pragma unroll
        for (int r = 0; r < 3; r++)
#pragma unroll
            for (int c = r + 1; c < 3; c++) {
                float s = 0.f;
#pragma unroll
                for (int k = 0; k < 3; k++) s += v[k * 3 + r] * v[k * 3 + c];
                sts_swU(dst, col, 12 + idx, 2.0f * s);
                idx++;
            }
    }
    sts_swU(dst, col, 15, 0.f);
}

__device__ __forceinline__ void prep3_V(const float* __restrict__ in0, int j,
                                        float* dst, int col) {
    float a[9];
    float ss = 0.f;
#pragma unroll
    for (int k = 0; k < 9; k++) { a[k] = in0[j * 9 + k]; ss += a[k] * a[k]; }
    float inv_n = 1.0f / (sqrtf(ss) + 1e-8f);
#pragma unroll
    for (int k = 0; k < 9; k++) a[k] *= inv_n;

#pragma unroll
    for (int r = 0; r < 3; r++)
#pragma unroll
        for (int k = 0; k < 3; k++)
            sts_swV(dst, col, r * 3 + k, -2.0f * a[k * 3 + r]);
#pragma unroll
    for (int d = 0; d < 3; d++) {
        float s = 0.f;
#pragma unroll
        for (int k = 0; k < 3; k++) s += a[d * 3 + k] * a[d * 3 + k];
        sts_swV(dst, col, 9 + d, s);
    }
    {
        int idx = 0;
#pragma unroll
        for (int r = 0; r < 3; r++)
#pragma unroll
            for (int c = r + 1; c < 3; c++) {
                float s = 0.f;
#pragma unroll
                for (int k = 0; k < 3; k++) s += a[r * 3 + k] * a[c * 3 + k];
                sts_swV(dst, col, 12 + idx, s);
                idx++;
            }
    }
    sts_swV(dst, col, 15, 0.f);
}

// ---------------------------------------------------------------------------
// layer-1 prep (5x5).  U row: [A(25), G_diag(5), 2*G_upper(10)]  (K1 = 40)
//                      V row: [-2*B^T(25), H_diag(5), H_upper(10)]
// ---------------------------------------------------------------------------
__device__ __forceinline__ void prep5_U(const float* __restrict__ in1, int i,
                                        float* dst, int col) {
    float m[5][10];
    float ss = 0.f;
#pragma unroll
    for (int r = 0; r < 5; r++)
#pragma unroll
        for (int c = 0; c < 5; c++) {
            float x = in1[i * 25 + r * 5 + c];
            m[r][c] = x; ss += x * x;
            m[r][c + 5] = (r == c) ? 1.0f : 0.0f;
        }
    float inv_n = 1.0f / (sqrtf(ss) + 1e-8f);
#pragma unroll
    for (int r = 0; r < 5; r++)
#pragma unroll
        for (int c = 0; c < 5; c++) m[r][c] *= inv_n;

#pragma unroll
    for (int col_ = 0; col_ < 5; col_++) {
#pragma unroll
        for (int r2 = 0; r2 < 5; r2++) {
            if (r2 > col_) {
                bool sw = fabsf(m[r2][col_]) > fabsf(m[col_][col_]);
#pragma unroll
                for (int c = 0; c < 10; c++) {
                    float x = m[col_][c], y = m[r2][c];
                    m[col_][c] = sw ? y : x;
                    m[r2][c]   = sw ? x : y;
                }
            }
        }
        float piv = 1.0f / m[col_][col_];
#pragma unroll
        for (int c = 0; c < 10; c++) m[col_][c] *= piv;
#pragma unroll
        for (int r = 0; r < 5; r++) {
            if (r == col_) continue;
            float f = m[r][col_];
#pragma unroll
            for (int c = 0; c < 10; c++) m[r][c] = fmaf(-f, m[col_][c], m[r][c]);
        }
    }

#pragma unroll
    for (int r = 0; r < 5; r++)
#pragma unroll
        for (int c = 0; c < 5; c++)
            sts_swU(dst, col, r * 5 + c, m[r][c + 5]);
#pragma unroll
    for (int d = 0; d < 5; d++) {
        float s = 0.f;
#pragma unroll
        for (int k = 0; k < 5; k++) s += m[k][d + 5] * m[k][d + 5];
        sts_swU(dst, col, 25 + d, s);
    }
    {
        int idx = 0;
#pragma unroll
        for (int r = 0; r < 5; r++)
#pragma unroll
            for (int c = r + 1; c < 5; c++) {
                float s = 0.f;
#pragma unroll
                for (int k = 0; k < 5; k++) s += m[k][r + 5] * m[k][c + 5];
                sts_swU(dst, col, 30 + idx, 2.0f * s);
                idx++;
            }
    }
}

__device__ __forceinline__ void prep5_V(const float* __restrict__ in1, int j,
                                        float* dst, int col) {
    float b[25];
    float ss = 0.f;
#pragma unroll
    for (int k = 0; k < 25; k++) { b[k] = in1[j * 25 + k]; ss += b[k] * b[k]; }
    float inv_n = 1.0f / (sqrtf(ss) + 1e-8f);
#pragma unroll
    for (int k = 0; k < 25; k++) b[k] *= inv_n;

#pragma unroll
    for (int r = 0; r < 5; r++)
#pragma unroll
        for (int k = 0; k < 5; k++)
            sts_swV(dst, col, r * 5 + k, -2.0f * b[k * 5 + r]);
#pragma unroll
    for (int d = 0; d < 5; d++) {
        float s = 0.f;
#pragma unroll
        for (int k = 0; k < 5; k++) s += b[d * 5 + k] * b[d * 5 + k];
        sts_swV(dst, col, 25 + d, s);
    }
    {
        int idx = 0;
#pragma unroll
        for (int r = 0; r < 5; r++)
#pragma unroll
            for (int c = r + 1; c < 5; c++) {
                float s = 0.f;
#pragma unroll
                for (int k = 0; k < 5; k++) s += b[r * 5 + k] * b[c * 5 + k];
                sts_swV(dst, col, 30 + idx, s);
                idx++;
            }
    }
}

// ---------------------------------------------------------------------------
// Mainloop + epilogue for a 32x64 tile, micro 4x4 (128 threads: 8 ty x 16 tx)
// ---------------------------------------------------------------------------
template <int LAYER, int UNROLL>
__device__ __forceinline__ float tile_mainloop(const float* Us, const float* Vs,
                                               int i0, int j0, bool diag, int tid) {
    constexpr int K = LAYER ? K1 : K0;
    constexpr float D = LAYER ? 5.0f : 3.0f;

    int tx = tid & 15, ty = tid >> 4;   // 16 col-groups x 8 row-groups
    float acc[16];
#pragma unroll
    for (int q = 0; q < 16; q++) acc[q] = 0.f;

#pragma unroll UNROLL
    for (int k = 0; k < K; k++) {
        int kc = k >> 2;
        float4 a = *(const float4*)&Us[k * 32 + (((ty ^ kc) & 7) << 2)];
        float4 b = *(const float4*)&Vs[k * 64 + (((tx ^ kc) & 15) << 2)];
        acc[0]  = fmaf(a.x, b.x, acc[0]);  acc[1]  = fmaf(a.x, b.y, acc[1]);
        acc[2]  = fmaf(a.x, b.z, acc[2]);  acc[3]  = fmaf(a.x, b.w, acc[3]);
        acc[4]  = fmaf(a.y, b.x, acc[4]);  acc[5]  = fmaf(a.y, b.y, acc[5]);
        acc[6]  = fmaf(a.y, b.z, acc[6]);  acc[7]  = fmaf(a.y, b.w, acc[7]);
        acc[8]  = fmaf(a.z, b.x, acc[8]);  acc[9]  = fmaf(a.z, b.y, acc[9]);
        acc[10] = fmaf(a.z, b.z, acc[10]); acc[11] = fmaf(a.z, b.w, acc[11]);
        acc[12] = fmaf(a.w, b.x, acc[12]); acc[13] = fmaf(a.w, b.y, acc[13]);
        acc[14] = fmaf(a.w, b.z, acc[14]); acc[15] = fmaf(a.w, b.w, acc[15]);
    }

    // min-scan early-out: any d2 = D + acc < 1  <=>  min(acc) < 1 - D
    float mn = acc[0];
#pragma unroll
    for (int q = 1; q < 16; q++) mn = fminf(mn, acc[q]);

    float val = 0.f;
    if (mn < 1.0f - D) {
        if (!diag) {
#pragma unroll
            for (int q = 0; q < 16; q++) val += loss_term(D + acc[q]);
        } else {
            int ib = i0 + ty * 4, jb = j0 + tx * 4;
#pragma unroll
            for (int r = 0; r < 4; r++)
#pragma unroll
                for (int c = 0; c < 4; c++)
                    if (ib + r > jb + c) val += loss_term(D + acc[r * 4 + c]);
        }
    }
    return val;
}

// trapezoid decode: (by, bx) with by >= 2*bx; cumulative C(bx) = bx*(NBY+1-bx)
template <int NBY, int NBX>
__device__ __forceinline__ void trap_decode(int t, int& by, int& bx) {
    int x = 0;
    while (x + 1 < NBX && (x + 1) * (NBY + 1 - (x + 1)) <= t) x++;
    bx = x;
    by = 2 * x + (t - x * (NBY + 1 - x));
}

// ---------------------------------------------------------------------------
// Fully self-contained blocks: redundant prep -> GEMM -> reduce -> finalize
// ---------------------------------------------------------------------------
__global__ __launch_bounds__(128, 8) void fused_kernel(const float* __restrict__ in0,
                                                       const float* __restrict__ in1,
                                                       float* __restrict__ out) {
    __shared__ float smem[K1 * 32 + K1 * 64];   // 15.4 KB (layer1 worst case)
    int tid = threadIdx.x;
    int b = blockIdx.x;

    bool layer1 = (b < NTILE1);           // heavier tiles on low block ids
    float val;
    if (layer1) {
        float* Us = smem;
        float* Vs = smem + K1 * 32;
        int by, bx; trap_decode<NBY1, NBX1>(b, by, bx);
        int i0 = by * 32, j0 = bx * 64;
        if (tid < 32)       prep5_U(in1, i0 + tid, Us, tid);
        else if (tid < 96)  prep5_V(in1, j0 + tid - 32, Vs, tid - 32);
        __syncthreads();
        val = tile_mainloop<1, 4>(Us, Vs, i0, j0, by < 2 * bx + 2, tid);
    } else {
        float* Us = smem;
        float* Vs = smem + K0 * 32;
        int by, bx; trap_decode<NBY0, NBX0>(b - NTILE1, by, bx);
        int i0 = by * 32, j0 = bx * 64;
        if (tid < 32)       prep3_U(in0, i0 + tid, Us, tid);
        else if (tid < 96)  prep3_V(in0, j0 + tid - 32, Vs, tid - 32);
        __syncthreads();
        val = tile_mainloop<0, 16>(Us, Vs, i0, j0, by < 2 * bx + 2, tid);
    }

#pragma unroll
    for (int o = 16; o > 0; o >>= 1)
        val += __shfl_down_sync(0xffffffffu, val, o);

    __syncthreads();   // smem main-loop reads done before reuse
    if ((tid & 31) == 0) smem[tid >> 5] = val;
    __syncthreads();

    if (tid == 0) {
        float s = smem[0] + smem[1] + smem[2] + smem[3];
        if (s != 0.0f)
            atomicAdd(layer1 ? &g_acc1 : &g_acc0, (double)s);
        __threadfence();
        unsigned done = atomicAdd(&g_count, 1u) + 1u;
        if (done == (unsigned)GRID_ALL) {
            double a0 = atomicAdd(&g_acc0, 0.0);
            double a1 = atomicAdd(&g_acc1, 0.0);
            double l0 = 2.0 * a0 / ((double)N0 * (double)(N0 - 1));
            double l1 = 2.0 * a1 / ((double)N1 * (double)(N1 - 1));
            out[0] = (float)(0.5 * (l0 + l1));
            // self-clean for the next graph replay (zero-invariant at entry)
            g_acc0 = 0.0; g_acc1 = 0.0;
            __threadfence();
            g_count = 0u;
        }
    }
}

extern "C" void kernel_launch(void* const* d_in, const int* in_sizes, int n_in,
                              void* d_out, int out_size) {
    const float* k0 = (const float*)d_in[0];
    const float* k1 = (const float*)d_in[1];
    float* out = (float*)d_out;
    fused_kernel<<<GRID_ALL, 128>>>(k0, k1, out);
}